// round 13
// baseline (speedup 1.0000x reference)
#include <cuda_runtime.h>
#include <cuda_bf16.h>
#include <cstdint>

#define Bc 2
#define Lc 2048
#define Hc 16
#define BHc 32
#define BM 128                 // q-rows per CTA
#define BN 64                  // s-rows per tile
#define NQT 16                 // q tiles
#define NST 32                 // s tiles
#define NCH 32                 // 64-row V-sum chunks
#define TILE_B 16384           // packed tile: Kf16(8K)|Vf16(8K)
#define NSTG 4                 // pipeline stages

// ---------------- device scratch ----------------
__device__ float g_part[2048 * 64];                             // per-convert-block V partial sums
__device__ float g_csum[BHc * NCH * 64];                        // exclusive suffix of 64-chunk V sums
__device__ unsigned char g_KV[(size_t)BHc * NST * TILE_B];      // pre-swizzled packed KV (16MB)
__device__ unsigned int g_ctr[BHc];                             // per-bh completion counters (self-reset)

// ---------------- helpers ----------------
__device__ __forceinline__ uint32_t smem_u32(const void* p) {
    uint32_t a;
    asm("{ .reg .u64 t; cvta.to.shared.u64 t, %1; cvt.u32.u64 %0, t; }" : "=r"(a) : "l"(p));
    return a;
}
__device__ __forceinline__ float ex2f(float x) {
    float y; asm("ex2.approx.f32 %0, %1;" : "=f"(y) : "f"(x)); return y;
}
__device__ __forceinline__ uint32_t packf16(float lo, float hi) {
    uint32_t r;
    asm("cvt.rn.f16x2.f32 %0, %1, %2;" : "=r"(r) : "f"(hi), "f"(lo));
    return r;
}
__device__ __forceinline__ void mma16816h(float* c, const uint32_t* a, uint32_t b0, uint32_t b1) {
    asm volatile("mma.sync.aligned.m16n8k16.row.col.f32.f16.f16.f32 "
        "{%0,%1,%2,%3}, {%4,%5,%6,%7}, {%8,%9}, {%0,%1,%2,%3};"
        : "+f"(c[0]), "+f"(c[1]), "+f"(c[2]), "+f"(c[3])
        : "r"(a[0]), "r"(a[1]), "r"(a[2]), "r"(a[3]), "r"(b0), "r"(b1));
}
__device__ __forceinline__ void ldsm4(uint32_t addr, uint32_t* r) {
    asm volatile("ldmatrix.sync.aligned.m8n8.x4.shared.b16 {%0,%1,%2,%3}, [%4];"
        : "=r"(r[0]), "=r"(r[1]), "=r"(r[2]), "=r"(r[3]) : "r"(addr));
}
__device__ __forceinline__ void ldsm4t(uint32_t addr, uint32_t* r) {
    asm volatile("ldmatrix.sync.aligned.m8n8.x4.trans.shared.b16 {%0,%1,%2,%3}, [%4];"
        : "=r"(r[0]), "=r"(r[1]), "=r"(r[2]), "=r"(r[3]) : "r"(addr));
}
__device__ __forceinline__ void bulk_ld(uint32_t dst, const void* src, uint32_t bytes, uint32_t mbar) {
    asm volatile("cp.async.bulk.shared::cluster.global.mbarrier::complete_tx::bytes [%0], [%1], %2, [%3];"
        :: "r"(dst), "l"(src), "r"(bytes), "r"(mbar) : "memory");
}
#define MBAR_INIT(addr, cnt) \
    asm volatile("mbarrier.init.shared.b64 [%0], %1;" :: "r"((uint32_t)(addr)), "r"((uint32_t)(cnt)) : "memory")
#define MBAR_EXPECT_TX(addr, tx) \
    asm volatile("mbarrier.arrive.expect_tx.shared.b64 _, [%0], %1;" :: "r"((uint32_t)(addr)), "r"((uint32_t)(tx)) : "memory")
#define MBAR_ARRIVE(addr) \
    asm volatile("mbarrier.arrive.shared.b64 _, [%0];" :: "r"((uint32_t)(addr)) : "memory")
#define MBAR_WAIT(addr, par) do { \
    uint32_t _m = (uint32_t)(addr); uint32_t _p = (uint32_t)(par); uint32_t _d; \
    asm volatile("{ .reg .pred p; mbarrier.try_wait.parity.acquire.cta.shared::cta.b64 p, [%1], %2; selp.b32 %0,1,0,p; }" \
        : "=r"(_d) : "r"(_m), "r"(_p) : "memory"); \
    if (!_d) { \
        asm volatile("{ .reg .pred P1; WL_%=: mbarrier.try_wait.parity.acquire.cta.shared::cta.b64 P1, [%0], %1, 0x989680; @P1 bra.uni WD_%=; bra.uni WL_%=; WD_%=: }" \
            :: "r"(_m), "r"(_p) : "memory"); \
    } } while (0)

// ---------------- preprocessing (single fused kernel, validated R12) ----------------
// K,V -> fp16, packed + XOR-swizzled tile layout; per-block V partial sums;
// the LAST block of each bh performs the exclusive suffix scan (counter self-resets).
__global__ void convert_kv(const float* __restrict__ K, const float* __restrict__ V) {
    __shared__ float vsum[32 * 64];                  // [s_local 32][d 64]
    __shared__ bool amLast;
    uint32_t n = blockIdx.x * 256 + threadIdx.x;     // 524288 threads
    int ch = n & 7;
    int s  = (n >> 3) & 2047;
    int bh = n >> 14;                                // == blockIdx.x >> 6
    int b = bh >> 4, h = bh & 15;
    int t = s >> 6, sr = s & 63;

    size_t src = (((size_t)b * Lc + s) * Hc + h) * 64 + ch * 8;
    size_t tb = ((size_t)(bh * NST + t)) * TILE_B;
    uint32_t roff = (uint32_t)sr * 128 + (((uint32_t)ch * 16) ^ (((uint32_t)sr & 7) << 4));

    float4 k0 = *(const float4*)(K + src), k1 = *(const float4*)(K + src + 4);
    float4 v0 = *(const float4*)(V + src), v1 = *(const float4*)(V + src + 4);

    uint4 kh, vh;
    kh.x = packf16(k0.x, k0.y); kh.y = packf16(k0.z, k0.w);
    kh.z = packf16(k1.x, k1.y); kh.w = packf16(k1.z, k1.w);
    vh.x = packf16(v0.x, v0.y); vh.y = packf16(v0.z, v0.w);
    vh.z = packf16(v1.x, v1.y); vh.w = packf16(v1.z, v1.w);

    *(uint4*)(g_KV + tb +    0 + roff) = kh;
    *(uint4*)(g_KV + tb + 8192 + roff) = vh;

    // block-level V column sums (32 s-rows per block)
    int sl = threadIdx.x >> 3;
    float* vs = &vsum[sl * 64 + ch * 8];
    *(float4*)&vs[0] = v0;
    *(float4*)&vs[4] = v1;
    __syncthreads();
    if (threadIdx.x < 64) {
        float acc = 0.f;
        #pragma unroll 8
        for (int r = 0; r < 32; ++r) acc += vsum[r * 64 + threadIdx.x];
        g_part[(uint32_t)blockIdx.x * 64 + threadIdx.x] = acc;
    }
    __syncthreads();

    // last block of this bh performs the suffix scan
    __threadfence();
    if (threadIdx.x == 0)
        amLast = (atomicAdd(&g_ctr[bh], 1u) == 63u);
    __syncthreads();
    if (amLast) {
        if (threadIdx.x < 64) {
            int d = threadIdx.x;
            float run = 0.f;
            #pragma unroll
            for (int c = NCH - 1; c >= 0; --c) {
                float ssum = g_part[(uint32_t)(bh * 64 + 2 * c) * 64 + d]
                           + g_part[(uint32_t)(bh * 64 + 2 * c + 1) * 64 + d];
                g_csum[(bh * NCH + c) * 64 + d] = run;   // exclusive: chunks > c
                run += ssum;
            }
        }
        if (threadIdx.x == 0) g_ctr[bh] = 0;             // reset for graph replay
    }
}

// ---------------- main attention kernel (R9 structure — best measured) ----------------
#define QSCALE 0.18033688011112042f   // 0.125 * log2(e)
#define ONES2  0x3C003C00u            // two fp16 1.0
#define SM_FULL0  (NSTG * TILE_B)         // full[4]: tx barriers
#define SM_EMPTY0 (NSTG * TILE_B + 32)    // empty[4]: 8 warp-arrival barriers
#define SM_TOTAL  (NSTG * TILE_B + 128)   // 65664 -> 2 CTAs/SM

extern __shared__ __align__(1024) char dynsm[];

// one s-tile: wait full -> QK MMAs -> V prefetch -> exp/pack -> den MMA -> PV MMAs -> arrive -> refill
template <bool MASKED>
__device__ __forceinline__ void tile_body(
    int t, int st, int rpar, int tmax_glob, uint32_t sm, const unsigned char* kvbase,
    const uint32_t Qh[4][4],
    float Oa[8][4], float Dden[4],
    int tid, int lane, int rowglob,
    int ks_row, uint32_t k_col, int vs_row, uint32_t v_col, uint32_t xo)
{
    MBAR_WAIT(sm + SM_FULL0 + st * 8, rpar);

    const uint32_t stg = sm + (uint32_t)st * TILE_B;
    const uint32_t k_b = stg, v_b = stg + 8192;

    // ---- S = Q Kt (single fp16) ----
    float S[8][4];
    #pragma unroll
    for (int i = 0; i < 8; ++i)
        #pragma unroll
        for (int j = 0; j < 4; ++j) S[i][j] = 0.f;

    #pragma unroll
    for (int kc = 0; kc < 4; ++kc) {
        #pragma unroll
        for (int nbp = 0; nbp < 4; ++nbp) {
            uint32_t off = (uint32_t)(nbp * 16 + ks_row) * 128
                         + (((uint32_t)kc * 32 + k_col) ^ xo);
            uint32_t kb[4];
            ldsm4(k_b + off, kb);
            mma16816h(S[2*nbp],   Qh[kc], kb[0], kb[1]);
            mma16816h(S[2*nbp+1], Qh[kc], kb[2], kb[3]);
        }
    }

    // ---- prefetch V for kcs=0 (overlaps the exp MUFU stretch) ----
    uint32_t vbuf[2][4][4];
    #pragma unroll
    for (int nbp = 0; nbp < 4; ++nbp) {
        uint32_t off = (uint32_t)(vs_row) * 128 + (((uint32_t)nbp * 32 + v_col) ^ xo);
        ldsm4t(v_b + off, vbuf[0][nbp]);
    }

    // ---- exp; masked (future) slots contribute exp(0)=1 (reference semantics) ----
    const int quad = lane & 3;
    const int lim0 = MASKED ? (rowglob - (t << 6)) : 0;
    const int lim1 = lim0 + 8;
    uint32_t Ph[4][4];
    #pragma unroll
    for (int nb = 0; nb < 8; ++nb) {
        float p0, p1, p2, p3;
        if (MASKED) {
            int s0 = nb * 8 + quad * 2;
            p0 = (s0     <= lim0) ? ex2f(S[nb][0]) : 1.f;
            p1 = (s0 + 1 <= lim0) ? ex2f(S[nb][1]) : 1.f;
            p2 = (s0     <= lim1) ? ex2f(S[nb][2]) : 1.f;
            p3 = (s0 + 1 <= lim1) ? ex2f(S[nb][3]) : 1.f;
        } else {
            p0 = ex2f(S[nb][0]);
            p1 = ex2f(S[nb][1]);
            p2 = ex2f(S[nb][2]);
            p3 = ex2f(S[nb][3]);
        }
        Ph[nb >> 1][(nb & 1) * 2]     = packf16(p0, p1);
        Ph[nb >> 1][(nb & 1) * 2 + 1] = packf16(p2, p3);
    }

    // ---- den += P * ones (row sums on tensor pipe) ----
    #pragma unroll
    for (int kcs = 0; kcs < 4; ++kcs)
        mma16816h(Dden, Ph[kcs], ONES2, ONES2);

    // ---- O += P V (rotated V buffers) ----
    #pragma unroll
    for (int kcs = 0; kcs < 4; ++kcs) {
        if (kcs < 3) {
            #pragma unroll
            for (int nbp = 0; nbp < 4; ++nbp) {
                uint32_t off = (uint32_t)((kcs + 1) * 16 + vs_row) * 128
                             + (((uint32_t)nbp * 32 + v_col) ^ xo);
                ldsm4t(v_b + off, vbuf[(kcs + 1) & 1][nbp]);
            }
        }
        #pragma unroll
        for (int nbp = 0; nbp < 4; ++nbp) {
            const uint32_t* vb = vbuf[kcs & 1][nbp];
            mma16816h(Oa[2*nbp],   Ph[kcs], vb[0], vb[1]);
            mma16816h(Oa[2*nbp+1], Ph[kcs], vb[2], vb[3]);
        }
    }

    // this warp is done reading stage st (MMA consumption guarantees ldsm completion)
    if (lane == 0) MBAR_ARRIVE(sm + SM_EMPTY0 + st * 8);

    // producer: refill stage once all 8 warps arrived
    if (tid == 0 && t + NSTG <= tmax_glob) {
        MBAR_WAIT(sm + SM_EMPTY0 + st * 8, rpar);
        MBAR_EXPECT_TX(sm + SM_FULL0 + st * 8, TILE_B);
        bulk_ld(stg, kvbase + (size_t)(t + NSTG) * TILE_B, TILE_B, sm + SM_FULL0 + st * 8);
    }
}

__global__ void __launch_bounds__(256, 2) attn_mma(const float* __restrict__ Q,
                                                   float* __restrict__ O) {
    const uint32_t sm = smem_u32(dynsm);
    const int tid = threadIdx.x;
    const int w = tid >> 5, lane = tid & 31;
    const int g = lane >> 2, quad = lane & 3;
    const int bh = blockIdx.y, b = bh >> 4, h = bh & 15;
    const int mtile = (NQT - 1) - (int)blockIdx.x;   // heavy q-tiles first
    const int tmax_glob = 2 * mtile + 1;             // max s-tile any warp needs
    // warps 0-3 (rows 0-63): the tile past the diagonal is ALL-masked (p=1) -> skip it
    const int nproc = 2 * mtile + 2 - (w < 4 ? 1 : 0);   // tiles processed; last one MASKED

    if (tid == 0) {
        #pragma unroll
        for (int s = 0; s < NSTG; ++s) {
            MBAR_INIT(sm + SM_FULL0 + s * 8, 1);
            MBAR_INIT(sm + SM_EMPTY0 + s * 8, 8);
        }
    }
    __syncthreads();   // mbarrier init visible to all warps

    // prologue FIRST: TMA fills overlap the Q global loads below
    const unsigned char* kvbase = g_KV + (size_t)bh * NST * TILE_B;
    if (tid == 0) {
        #pragma unroll
        for (int s = 0; s < NSTG; ++s) {
            if (s <= tmax_glob) {
                MBAR_EXPECT_TX(sm + SM_FULL0 + s * 8, TILE_B);
                bulk_ld(sm + s * TILE_B, kvbase + (size_t)s * TILE_B, TILE_B,
                        sm + SM_FULL0 + s * 8);
            }
        }
    }

    // per-lane ldmatrix geometry (XOR-swizzled, 128B rows)
    const int ks_row = (lane & 7) + ((lane >> 4) << 3);
    const uint32_t k_col = ((uint32_t)((lane >> 3) & 1)) * 16;
    const int vs_row = (lane & 7) + (((lane >> 3) & 1) << 3);
    const uint32_t v_col = ((uint32_t)(lane >> 4)) << 4;
    const uint32_t xo = ((uint32_t)(lane & 7)) << 4;

    // ---- Q fragments (single fp16, scale folded in) ----
    uint32_t Qh[4][4];
    {
        const float* qb = Q + (((size_t)b * Lc + (size_t)mtile * BM + w * 16) * Hc + h) * 64;
        #pragma unroll
        for (int kc = 0; kc < 4; ++kc) {
            int e0 = kc * 16 + quad * 2;
            float2 v00 = *(const float2*)(qb + (size_t)g * 1024 + e0);
            float2 v10 = *(const float2*)(qb + (size_t)(g + 8) * 1024 + e0);
            float2 v01 = *(const float2*)(qb + (size_t)g * 1024 + e0 + 8);
            float2 v11 = *(const float2*)(qb + (size_t)(g + 8) * 1024 + e0 + 8);
            Qh[kc][0] = packf16(v00.x * QSCALE, v00.y * QSCALE);
            Qh[kc][1] = packf16(v10.x * QSCALE, v10.y * QSCALE);
            Qh[kc][2] = packf16(v01.x * QSCALE, v01.y * QSCALE);
            Qh[kc][3] = packf16(v11.x * QSCALE, v11.y * QSCALE);
        }
    }

    float Oa[8][4];
    #pragma unroll
    for (int i = 0; i < 8; ++i)
        #pragma unroll
        for (int j = 0; j < 4; ++j) Oa[i][j] = 0.f;
    float Dden[4] = {0.f, 0.f, 0.f, 0.f};

    const int rowA = w * 16 + g;
    const int rowglob = mtile * BM + rowA;

    int t = 0, st = 0, rp = 0;
    #pragma unroll 1
    for (; t < nproc - 1; ++t) {
        tile_body<false>(t, st, rp, tmax_glob, sm, kvbase, Qh, Oa, Dden,
                         tid, lane, rowglob, ks_row, k_col, vs_row, v_col, xo);
        if (++st == NSTG) { st = 0; rp ^= 1; }
    }
    tile_body<true>(t, st, rp, tmax_glob, sm, kvbase, Qh, Oa, Dden,
                    tid, lane, rowglob, ks_row, k_col, vs_row, v_col, xo);

    // ---- epilogue ----
    // Dden[0]/Dden[2] hold full row sums (rows g, g+8) — no shuffle needed.
    const float corr = (float)(Lc - BN * nproc);   // masked slots beyond processed tiles
    const float inv0 = 1.f / (Dden[0] + corr);
    const float inv1 = 1.f / (Dden[2] + corr);

    const int r0g = rowglob;
    const int r1g = r0g + 8;
    const size_t ob0 = (((size_t)b * Lc + r0g) * Hc + h) * 64;
    const size_t ob1 = (((size_t)b * Lc + r1g) * Hc + h) * 64;
    const float* sfx = &g_csum[(bh * NCH + (nproc - 1)) * 64];  // V-sum over chunks >= nproc

    #pragma unroll
    for (int nb = 0; nb < 8; ++nb) {
        int d0 = nb * 8 + quad * 2;
        float2 s2 = *(const float2*)(sfx + d0);
        float2 o0 = make_float2((Oa[nb][0] + s2.x) * inv0, (Oa[nb][1] + s2.y) * inv0);
        float2 o1 = make_float2((Oa[nb][2] + s2.x) * inv1, (Oa[nb][3] + s2.y) * inv1);
        *(float2*)&O[ob0 + d0] = o0;
        *(float2*)&O[ob1 + d0] = o1;
    }
}

// ---------------- launch ----------------
extern "C" void kernel_launch(void* const* d_in, const int* in_sizes, int n_in,
                              void* d_out, int out_size) {
    const float* Q = (const float*)d_in[0];
    const float* K = (const float*)d_in[1];
    const float* V = (const float*)d_in[2];
    float* O = (float*)d_out;

    convert_kv<<<2048, 256>>>(K, V);

    cudaFuncSetAttribute(attn_mma, cudaFuncAttributeMaxDynamicSharedMemorySize, SM_TOTAL);
    attn_mma<<<dim3(NQT, BHc), 256, SM_TOTAL>>>(Q, O);
}

// round 14
// speedup vs baseline: 1.0263x; 1.0263x over previous
#include <cuda_runtime.h>
#include <cuda_bf16.h>
#include <cstdint>

#define Bc 2
#define Lc 2048
#define Hc 16
#define BHc 32
#define BM 128                 // q-rows per CTA
#define BN 64                  // s-rows per tile
#define NQT 16                 // q tiles
#define NST 32                 // s tiles
#define NCH 32                 // 64-row V-sum chunks
#define TILE_B 16384           // packed tile: Kf16(8K)|Vf16(8K)
#define NSTG 4                 // pipeline stages

// ---------------- device scratch ----------------
__device__ float g_part[2048 * 64];                             // per-convert-block V partial sums
__device__ float g_csum[BHc * NCH * 64];                        // exclusive suffix of 64-chunk V sums
__device__ unsigned char g_KV[(size_t)BHc * NST * TILE_B];      // pre-swizzled packed KV (16MB)
__device__ unsigned int g_ctr[BHc];                             // per-bh completion counters (self-reset)

// ---------------- helpers ----------------
__device__ __forceinline__ uint32_t smem_u32(const void* p) {
    uint32_t a;
    asm("{ .reg .u64 t; cvta.to.shared.u64 t, %1; cvt.u32.u64 %0, t; }" : "=r"(a) : "l"(p));
    return a;
}
__device__ __forceinline__ float ex2f(float x) {
    float y; asm("ex2.approx.f32 %0, %1;" : "=f"(y) : "f"(x)); return y;
}
__device__ __forceinline__ uint32_t packf16(float lo, float hi) {
    uint32_t r;
    asm("cvt.rn.f16x2.f32 %0, %1, %2;" : "=r"(r) : "f"(hi), "f"(lo));
    return r;
}
// accumulate form: d += a*b
__device__ __forceinline__ void mma16816h(float* c, const uint32_t* a, uint32_t b0, uint32_t b1) {
    asm volatile("mma.sync.aligned.m16n8k16.row.col.f32.f16.f16.f32 "
        "{%0,%1,%2,%3}, {%4,%5,%6,%7}, {%8,%9}, {%0,%1,%2,%3};"
        : "+f"(c[0]), "+f"(c[1]), "+f"(c[2]), "+f"(c[3])
        : "r"(a[0]), "r"(a[1]), "r"(a[2]), "r"(a[3]), "r"(b0), "r"(b1));
}
// explicit-C form: d = a*b + c  (used with pinned zero C to skip S pre-zeroing)
__device__ __forceinline__ void mma16816hc(float* d, const uint32_t* a, uint32_t b0, uint32_t b1,
                                           const float* c) {
    asm volatile("mma.sync.aligned.m16n8k16.row.col.f32.f16.f16.f32 "
        "{%0,%1,%2,%3}, {%4,%5,%6,%7}, {%8,%9}, {%10,%11,%12,%13};"
        : "=f"(d[0]), "=f"(d[1]), "=f"(d[2]), "=f"(d[3])
        : "r"(a[0]), "r"(a[1]), "r"(a[2]), "r"(a[3]), "r"(b0), "r"(b1),
          "f"(c[0]), "f"(c[1]), "f"(c[2]), "f"(c[3]));
}
__device__ __forceinline__ void ldsm4(uint32_t addr, uint32_t* r) {
    asm volatile("ldmatrix.sync.aligned.m8n8.x4.shared.b16 {%0,%1,%2,%3}, [%4];"
        : "=r"(r[0]), "=r"(r[1]), "=r"(r[2]), "=r"(r[3]) : "r"(addr));
}
__device__ __forceinline__ void ldsm4t(uint32_t addr, uint32_t* r) {
    asm volatile("ldmatrix.sync.aligned.m8n8.x4.trans.shared.b16 {%0,%1,%2,%3}, [%4];"
        : "=r"(r[0]), "=r"(r[1]), "=r"(r[2]), "=r"(r[3]) : "r"(addr));
}
__device__ __forceinline__ void bulk_ld(uint32_t dst, const void* src, uint32_t bytes, uint32_t mbar) {
    asm volatile("cp.async.bulk.shared::cluster.global.mbarrier::complete_tx::bytes [%0], [%1], %2, [%3];"
        :: "r"(dst), "l"(src), "r"(bytes), "r"(mbar) : "memory");
}
#define MBAR_INIT(addr, cnt) \
    asm volatile("mbarrier.init.shared.b64 [%0], %1;" :: "r"((uint32_t)(addr)), "r"((uint32_t)(cnt)) : "memory")
#define MBAR_EXPECT_TX(addr, tx) \
    asm volatile("mbarrier.arrive.expect_tx.shared.b64 _, [%0], %1;" :: "r"((uint32_t)(addr)), "r"((uint32_t)(tx)) : "memory")
#define MBAR_ARRIVE(addr) \
    asm volatile("mbarrier.arrive.shared.b64 _, [%0];" :: "r"((uint32_t)(addr)) : "memory")
#define MBAR_WAIT(addr, par) do { \
    uint32_t _m = (uint32_t)(addr); uint32_t _p = (uint32_t)(par); uint32_t _d; \
    asm volatile("{ .reg .pred p; mbarrier.try_wait.parity.acquire.cta.shared::cta.b64 p, [%1], %2; selp.b32 %0,1,0,p; }" \
        : "=r"(_d) : "r"(_m), "r"(_p) : "memory"); \
    if (!_d) { \
        asm volatile("{ .reg .pred P1; WL_%=: mbarrier.try_wait.parity.acquire.cta.shared::cta.b64 P1, [%0], %1, 0x989680; @P1 bra.uni WD_%=; bra.uni WL_%=; WD_%=: }" \
            :: "r"(_m), "r"(_p) : "memory"); \
    } } while (0)

// ---------------- preprocessing (single fused kernel, validated R12/R13) ----------------
__global__ void convert_kv(const float* __restrict__ K, const float* __restrict__ V) {
    __shared__ float vsum[32 * 64];                  // [s_local 32][d 64]
    __shared__ bool amLast;
    uint32_t n = blockIdx.x * 256 + threadIdx.x;     // 524288 threads
    int ch = n & 7;
    int s  = (n >> 3) & 2047;
    int bh = n >> 14;                                // == blockIdx.x >> 6
    int b = bh >> 4, h = bh & 15;
    int t = s >> 6, sr = s & 63;

    size_t src = (((size_t)b * Lc + s) * Hc + h) * 64 + ch * 8;
    size_t tb = ((size_t)(bh * NST + t)) * TILE_B;
    uint32_t roff = (uint32_t)sr * 128 + (((uint32_t)ch * 16) ^ (((uint32_t)sr & 7) << 4));

    float4 k0 = *(const float4*)(K + src), k1 = *(const float4*)(K + src + 4);
    float4 v0 = *(const float4*)(V + src), v1 = *(const float4*)(V + src + 4);

    uint4 kh, vh;
    kh.x = packf16(k0.x, k0.y); kh.y = packf16(k0.z, k0.w);
    kh.z = packf16(k1.x, k1.y); kh.w = packf16(k1.z, k1.w);
    vh.x = packf16(v0.x, v0.y); vh.y = packf16(v0.z, v0.w);
    vh.z = packf16(v1.x, v1.y); vh.w = packf16(v1.z, v1.w);

    *(uint4*)(g_KV + tb +    0 + roff) = kh;
    *(uint4*)(g_KV + tb + 8192 + roff) = vh;

    // block-level V column sums (32 s-rows per block)
    int sl = threadIdx.x >> 3;
    float* vs = &vsum[sl * 64 + ch * 8];
    *(float4*)&vs[0] = v0;
    *(float4*)&vs[4] = v1;
    __syncthreads();
    if (threadIdx.x < 64) {
        float acc = 0.f;
        #pragma unroll 8
        for (int r = 0; r < 32; ++r) acc += vsum[r * 64 + threadIdx.x];
        g_part[(uint32_t)blockIdx.x * 64 + threadIdx.x] = acc;
    }
    __syncthreads();

    // last block of this bh performs the suffix scan
    __threadfence();
    if (threadIdx.x == 0)
        amLast = (atomicAdd(&g_ctr[bh], 1u) == 63u);
    __syncthreads();
    if (amLast) {
        if (threadIdx.x < 64) {
            int d = threadIdx.x;
            float run = 0.f;
            #pragma unroll
            for (int c = NCH - 1; c >= 0; --c) {
                float ssum = g_part[(uint32_t)(bh * 64 + 2 * c) * 64 + d]
                           + g_part[(uint32_t)(bh * 64 + 2 * c + 1) * 64 + d];
                g_csum[(bh * NCH + c) * 64 + d] = run;   // exclusive: chunks > c
                run += ssum;
            }
        }
        if (threadIdx.x == 0) g_ctr[bh] = 0;             // reset for graph replay
    }
}

// ---------------- main attention kernel ----------------
#define QSCALE 0.18033688011112042f   // 0.125 * log2(e)
#define ONES2  0x3C003C00u            // two fp16 1.0
#define SM_FULL0  (NSTG * TILE_B)         // full[4]: tx barriers
#define SM_EMPTY0 (NSTG * TILE_B + 32)    // empty[4]: 8 warp-arrival barriers
#define SM_TOTAL  (NSTG * TILE_B + 128)   // 65664 -> 2 CTAs/SM

extern __shared__ __align__(1024) char dynsm[];

// one s-tile: wait full -> QK MMAs (zero-C first) -> V prefetch -> exp/pack -> den -> PV -> arrive -> refill
template <bool MASKED>
__device__ __forceinline__ void tile_body(
    int t, int st, int rpar, int tmax_glob, uint32_t sm, const unsigned char* kvbase,
    const uint32_t Qh[4][4], const uint32_t koff[4], const uint32_t voff[4],
    const float zc[4],
    float Oa[8][4], float Dden[4],
    int tid, int lane, int rowglob)
{
    MBAR_WAIT(sm + SM_FULL0 + st * 8, rpar);

    const uint32_t stg = sm + (uint32_t)st * TILE_B;
    const uint32_t k_b = stg, v_b = stg + 8192;

    // ---- S = Q Kt (single fp16); kc=0 uses explicit zero-C (no S pre-zeroing) ----
    float S[8][4];
    #pragma unroll
    for (int kc = 0; kc < 4; ++kc) {
        #pragma unroll
        for (int nbp = 0; nbp < 4; ++nbp) {
            uint32_t kb[4];
            ldsm4(k_b + koff[kc] + (uint32_t)nbp * 2048, kb);
            if (kc == 0) {
                mma16816hc(S[2*nbp],   Qh[0], kb[0], kb[1], zc);
                mma16816hc(S[2*nbp+1], Qh[0], kb[2], kb[3], zc);
            } else {
                mma16816h(S[2*nbp],   Qh[kc], kb[0], kb[1]);
                mma16816h(S[2*nbp+1], Qh[kc], kb[2], kb[3]);
            }
        }
    }

    // ---- prefetch V for kcs=0 (overlaps the exp MUFU stretch) ----
    uint32_t vbuf[2][4][4];
    #pragma unroll
    for (int nbp = 0; nbp < 4; ++nbp)
        ldsm4t(v_b + voff[nbp], vbuf[0][nbp]);

    // ---- exp; masked (future) slots contribute exp(0)=1 (reference semantics) ----
    const int quad = lane & 3;
    const int lim0 = MASKED ? (rowglob - (t << 6)) : 0;
    const int lim1 = lim0 + 8;
    uint32_t Ph[4][4];
    #pragma unroll
    for (int nb = 0; nb < 8; ++nb) {
        float p0, p1, p2, p3;
        if (MASKED) {
            int s0 = nb * 8 + quad * 2;
            p0 = (s0     <= lim0) ? ex2f(S[nb][0]) : 1.f;
            p1 = (s0 + 1 <= lim0) ? ex2f(S[nb][1]) : 1.f;
            p2 = (s0     <= lim1) ? ex2f(S[nb][2]) : 1.f;
            p3 = (s0 + 1 <= lim1) ? ex2f(S[nb][3]) : 1.f;
        } else {
            p0 = ex2f(S[nb][0]);
            p1 = ex2f(S[nb][1]);
            p2 = ex2f(S[nb][2]);
            p3 = ex2f(S[nb][3]);
        }
        Ph[nb >> 1][(nb & 1) * 2]     = packf16(p0, p1);
        Ph[nb >> 1][(nb & 1) * 2 + 1] = packf16(p2, p3);
    }

    // ---- den += P * ones (row sums on tensor pipe) ----
    #pragma unroll
    for (int kcs = 0; kcs < 4; ++kcs)
        mma16816h(Dden, Ph[kcs], ONES2, ONES2);

    // ---- O += P V (rotated V buffers) ----
    #pragma unroll
    for (int kcs = 0; kcs < 4; ++kcs) {
        if (kcs < 3) {
            #pragma unroll
            for (int nbp = 0; nbp < 4; ++nbp)
                ldsm4t(v_b + voff[nbp] + (uint32_t)(kcs + 1) * 2048, vbuf[(kcs + 1) & 1][nbp]);
        }
        #pragma unroll
        for (int nbp = 0; nbp < 4; ++nbp) {
            const uint32_t* vb = vbuf[kcs & 1][nbp];
            mma16816h(Oa[2*nbp],   Ph[kcs], vb[0], vb[1]);
            mma16816h(Oa[2*nbp+1], Ph[kcs], vb[2], vb[3]);
        }
    }

    // this warp is done reading stage st (MMA consumption guarantees ldsm completion)
    if (lane == 0) MBAR_ARRIVE(sm + SM_EMPTY0 + st * 8);

    // producer: refill stage once all 8 warps arrived
    if (tid == 0 && t + NSTG <= tmax_glob) {
        MBAR_WAIT(sm + SM_EMPTY0 + st * 8, rpar);
        MBAR_EXPECT_TX(sm + SM_FULL0 + st * 8, TILE_B);
        bulk_ld(stg, kvbase + (size_t)(t + NSTG) * TILE_B, TILE_B, sm + SM_FULL0 + st * 8);
    }
}

__global__ void __launch_bounds__(256, 2) attn_mma(const float* __restrict__ Q,
                                                   float* __restrict__ O) {
    const uint32_t sm = smem_u32(dynsm);
    const int tid = threadIdx.x;
    const int w = tid >> 5, lane = tid & 31;
    const int g = lane >> 2, quad = lane & 3;
    const int bh = blockIdx.y, b = bh >> 4, h = bh & 15;
    const int mtile = (NQT - 1) - (int)blockIdx.x;   // heavy q-tiles first
    const int tmax_glob = 2 * mtile + 1;             // max s-tile any warp needs
    // warps 0-3 (rows 0-63): the tile past the diagonal is ALL-masked (p=1) -> skip it
    const int nproc = 2 * mtile + 2 - (w < 4 ? 1 : 0);   // tiles processed; last one MASKED

    if (tid == 0) {
        #pragma unroll
        for (int s = 0; s < NSTG; ++s) {
            MBAR_INIT(sm + SM_FULL0 + s * 8, 1);
            MBAR_INIT(sm + SM_EMPTY0 + s * 8, 8);
        }
    }
    __syncthreads();   // mbarrier init visible to all warps

    // prologue FIRST: TMA fills overlap the Q global loads below
    const unsigned char* kvbase = g_KV + (size_t)bh * NST * TILE_B;
    if (tid == 0) {
        #pragma unroll
        for (int s = 0; s < NSTG; ++s) {
            if (s <= tmax_glob) {
                MBAR_EXPECT_TX(sm + SM_FULL0 + s * 8, TILE_B);
                bulk_ld(sm + s * TILE_B, kvbase + (size_t)s * TILE_B, TILE_B,
                        sm + SM_FULL0 + s * 8);
            }
        }
    }

    // per-lane ldmatrix geometry (XOR-swizzled, 128B rows), hoisted to offset tables
    const int ks_row = (lane & 7) + ((lane >> 4) << 3);
    const uint32_t k_col = ((uint32_t)((lane >> 3) & 1)) * 16;
    const int vs_row = (lane & 7) + (((lane >> 3) & 1) << 3);
    const uint32_t v_col = ((uint32_t)(lane >> 4)) << 4;
    const uint32_t xo = ((uint32_t)(lane & 7)) << 4;
    uint32_t koff[4], voff[4];
    #pragma unroll
    for (int kc = 0; kc < 4; ++kc)
        koff[kc] = (uint32_t)ks_row * 128 + (((uint32_t)kc * 32 + k_col) ^ xo);
    #pragma unroll
    for (int nbp = 0; nbp < 4; ++nbp)
        voff[nbp] = (uint32_t)vs_row * 128 + (((uint32_t)nbp * 32 + v_col) ^ xo);

    // ---- Q fragments (single fp16, scale folded in) ----
    uint32_t Qh[4][4];
    {
        const float* qb = Q + (((size_t)b * Lc + (size_t)mtile * BM + w * 16) * Hc + h) * 64;
        #pragma unroll
        for (int kc = 0; kc < 4; ++kc) {
            int e0 = kc * 16 + quad * 2;
            float2 v00 = *(const float2*)(qb + (size_t)g * 1024 + e0);
            float2 v10 = *(const float2*)(qb + (size_t)(g + 8) * 1024 + e0);
            float2 v01 = *(const float2*)(qb + (size_t)g * 1024 + e0 + 8);
            float2 v11 = *(const float2*)(qb + (size_t)(g + 8) * 1024 + e0 + 8);
            Qh[kc][0] = packf16(v00.x * QSCALE, v00.y * QSCALE);
            Qh[kc][1] = packf16(v10.x * QSCALE, v10.y * QSCALE);
            Qh[kc][2] = packf16(v01.x * QSCALE, v01.y * QSCALE);
            Qh[kc][3] = packf16(v11.x * QSCALE, v11.y * QSCALE);
        }
    }

    float Oa[8][4];
    #pragma unroll
    for (int i = 0; i < 8; ++i)
        #pragma unroll
        for (int j = 0; j < 4; ++j) Oa[i][j] = 0.f;
    float Dden[4] = {0.f, 0.f, 0.f, 0.f};
    const float zc[4] = {0.f, 0.f, 0.f, 0.f};

    const int rowA = w * 16 + g;
    const int rowglob = mtile * BM + rowA;

    int t = 0, st = 0, rp = 0;
    #pragma unroll 2
    for (; t < nproc - 1; ++t) {
        tile_body<false>(t, st, rp, tmax_glob, sm, kvbase, Qh, koff, voff, zc,
                         Oa, Dden, tid, lane, rowglob);
        if (++st == NSTG) { st = 0; rp ^= 1; }
    }
    tile_body<true>(t, st, rp, tmax_glob, sm, kvbase, Qh, koff, voff, zc,
                    Oa, Dden, tid, lane, rowglob);

    // ---- epilogue ----
    // Dden[0]/Dden[2] hold full row sums (rows g, g+8) — no shuffle needed.
    const float corr = (float)(Lc - BN * nproc);   // masked slots beyond processed tiles
    const float inv0 = 1.f / (Dden[0] + corr);
    const float inv1 = 1.f / (Dden[2] + corr);

    const int r0g = rowglob;
    const int r1g = r0g + 8;
    const size_t ob0 = (((size_t)b * Lc + r0g) * Hc + h) * 64;
    const size_t ob1 = (((size_t)b * Lc + r1g) * Hc + h) * 64;
    const float* sfx = &g_csum[(bh * NCH + (nproc - 1)) * 64];  // V-sum over chunks >= nproc

    #pragma unroll
    for (int nb = 0; nb < 8; ++nb) {
        int d0 = nb * 8 + quad * 2;
        float2 s2 = *(const float2*)(sfx + d0);
        float2 o0 = make_float2((Oa[nb][0] + s2.x) * inv0, (Oa[nb][1] + s2.y) * inv0);
        float2 o1 = make_float2((Oa[nb][2] + s2.x) * inv1, (Oa[nb][3] + s2.y) * inv1);
        *(float2*)&O[ob0 + d0] = o0;
        *(float2*)&O[ob1 + d0] = o1;
    }
}

// ---------------- launch ----------------
extern "C" void kernel_launch(void* const* d_in, const int* in_sizes, int n_in,
                              void* d_out, int out_size) {
    const float* Q = (const float*)d_in[0];
    const float* K = (const float*)d_in[1];
    const float* V = (const float*)d_in[2];
    float* O = (float*)d_out;

    convert_kv<<<2048, 256>>>(K, V);

    cudaFuncSetAttribute(attn_mma, cudaFuncAttributeMaxDynamicSharedMemorySize, SM_TOTAL);
    attn_mma<<<dim3(NQT, BHc), 256, SM_TOTAL>>>(Q, O);
}

// round 15
// speedup vs baseline: 1.0580x; 1.0309x over previous
#include <cuda_runtime.h>
#include <cuda_bf16.h>
#include <cstdint>

#define Bc 2
#define Lc 2048
#define Hc 16
#define BHc 32
#define BM 128                 // q-rows per CTA
#define BN 64                  // s-rows per tile
#define NQT 16                 // q tiles
#define NST 32                 // s tiles
#define TILE_B 16384           // packed tile: Kf16(8K)|Vf16(8K)
#define NSTG 4                 // pipeline stages

// ---------------- device scratch ----------------
__device__ float g_part[2048 * 64];                             // per-half-chunk (32 s-rows) V column sums
__device__ unsigned char g_KV[(size_t)BHc * NST * TILE_B];      // pre-swizzled packed KV (16MB)

// ---------------- helpers ----------------
__device__ __forceinline__ uint32_t smem_u32(const void* p) {
    uint32_t a;
    asm("{ .reg .u64 t; cvta.to.shared.u64 t, %1; cvt.u32.u64 %0, t; }" : "=r"(a) : "l"(p));
    return a;
}
__device__ __forceinline__ float ex2f(float x) {
    float y; asm("ex2.approx.f32 %0, %1;" : "=f"(y) : "f"(x)); return y;
}
__device__ __forceinline__ uint32_t packf16(float lo, float hi) {
    uint32_t r;
    asm("cvt.rn.f16x2.f32 %0, %1, %2;" : "=r"(r) : "f"(hi), "f"(lo));
    return r;
}
// accumulate form: d += a*b
__device__ __forceinline__ void mma16816h(float* c, const uint32_t* a, uint32_t b0, uint32_t b1) {
    asm volatile("mma.sync.aligned.m16n8k16.row.col.f32.f16.f16.f32 "
        "{%0,%1,%2,%3}, {%4,%5,%6,%7}, {%8,%9}, {%0,%1,%2,%3};"
        : "+f"(c[0]), "+f"(c[1]), "+f"(c[2]), "+f"(c[3])
        : "r"(a[0]), "r"(a[1]), "r"(a[2]), "r"(a[3]), "r"(b0), "r"(b1));
}
// explicit-C form: d = a*b + c  (pinned zero C skips S pre-zeroing)
__device__ __forceinline__ void mma16816hc(float* d, const uint32_t* a, uint32_t b0, uint32_t b1,
                                           const float* c) {
    asm volatile("mma.sync.aligned.m16n8k16.row.col.f32.f16.f16.f32 "
        "{%0,%1,%2,%3}, {%4,%5,%6,%7}, {%8,%9}, {%10,%11,%12,%13};"
        : "=f"(d[0]), "=f"(d[1]), "=f"(d[2]), "=f"(d[3])
        : "r"(a[0]), "r"(a[1]), "r"(a[2]), "r"(a[3]), "r"(b0), "r"(b1),
          "f"(c[0]), "f"(c[1]), "f"(c[2]), "f"(c[3]));
}
__device__ __forceinline__ void ldsm4(uint32_t addr, uint32_t* r) {
    asm volatile("ldmatrix.sync.aligned.m8n8.x4.shared.b16 {%0,%1,%2,%3}, [%4];"
        : "=r"(r[0]), "=r"(r[1]), "=r"(r[2]), "=r"(r[3]) : "r"(addr));
}
__device__ __forceinline__ void ldsm4t(uint32_t addr, uint32_t* r) {
    asm volatile("ldmatrix.sync.aligned.m8n8.x4.trans.shared.b16 {%0,%1,%2,%3}, [%4];"
        : "=r"(r[0]), "=r"(r[1]), "=r"(r[2]), "=r"(r[3]) : "r"(addr));
}
__device__ __forceinline__ void bulk_ld(uint32_t dst, const void* src, uint32_t bytes, uint32_t mbar) {
    asm volatile("cp.async.bulk.shared::cluster.global.mbarrier::complete_tx::bytes [%0], [%1], %2, [%3];"
        :: "r"(dst), "l"(src), "r"(bytes), "r"(mbar) : "memory");
}
#define MBAR_INIT(addr, cnt) \
    asm volatile("mbarrier.init.shared.b64 [%0], %1;" :: "r"((uint32_t)(addr)), "r"((uint32_t)(cnt)) : "memory")
#define MBAR_EXPECT_TX(addr, tx) \
    asm volatile("mbarrier.arrive.expect_tx.shared.b64 _, [%0], %1;" :: "r"((uint32_t)(addr)), "r"((uint32_t)(tx)) : "memory")
#define MBAR_ARRIVE(addr) \
    asm volatile("mbarrier.arrive.shared.b64 _, [%0];" :: "r"((uint32_t)(addr)) : "memory")
#define MBAR_WAIT(addr, par) do { \
    uint32_t _m = (uint32_t)(addr); uint32_t _p = (uint32_t)(par); uint32_t _d; \
    asm volatile("{ .reg .pred p; mbarrier.try_wait.parity.acquire.cta.shared::cta.b64 p, [%1], %2; selp.b32 %0,1,0,p; }" \
        : "=r"(_d) : "r"(_m), "r"(_p) : "memory"); \
    if (!_d) { \
        asm volatile("{ .reg .pred P1; WL_%=: mbarrier.try_wait.parity.acquire.cta.shared::cta.b64 P1, [%0], %1, 0x989680; @P1 bra.uni WD_%=; bra.uni WL_%=; WD_%=: }" \
            :: "r"(_m), "r"(_p) : "memory"); \
    } } while (0)

// ---------------- preprocessing: convert + per-block V sums (NO scan tail) ----------------
__global__ void convert_kv(const float* __restrict__ K, const float* __restrict__ V) {
    __shared__ float vsum[32 * 64];                  // [s_local 32][d 64]
    uint32_t n = blockIdx.x * 256 + threadIdx.x;     // 524288 threads
    int ch = n & 7;
    int s  = (n >> 3) & 2047;
    int bh = n >> 14;                                // == blockIdx.x >> 6
    int b = bh >> 4, h = bh & 15;
    int t = s >> 6, sr = s & 63;

    size_t src = (((size_t)b * Lc + s) * Hc + h) * 64 + ch * 8;
    size_t tb = ((size_t)(bh * NST + t)) * TILE_B;
    uint32_t roff = (uint32_t)sr * 128 + (((uint32_t)ch * 16) ^ (((uint32_t)sr & 7) << 4));

    float4 k0 = *(const float4*)(K + src), k1 = *(const float4*)(K + src + 4);
    float4 v0 = *(const float4*)(V + src), v1 = *(const float4*)(V + src + 4);

    uint4 kh, vh;
    kh.x = packf16(k0.x, k0.y); kh.y = packf16(k0.z, k0.w);
    kh.z = packf16(k1.x, k1.y); kh.w = packf16(k1.z, k1.w);
    vh.x = packf16(v0.x, v0.y); vh.y = packf16(v0.z, v0.w);
    vh.z = packf16(v1.x, v1.y); vh.w = packf16(v1.z, v1.w);

    *(uint4*)(g_KV + tb +    0 + roff) = kh;
    *(uint4*)(g_KV + tb + 8192 + roff) = vh;

    // block-level V column sums (32 s-rows per block) -> g_part[blockIdx.x][d]
    int sl = threadIdx.x >> 3;
    float* vs = &vsum[sl * 64 + ch * 8];
    *(float4*)&vs[0] = v0;
    *(float4*)&vs[4] = v1;
    __syncthreads();
    if (threadIdx.x < 64) {
        float acc = 0.f;
        #pragma unroll 8
        for (int r = 0; r < 32; ++r) acc += vsum[r * 64 + threadIdx.x];
        g_part[(uint32_t)blockIdx.x * 64 + threadIdx.x] = acc;
    }
}

// ---------------- main attention kernel (R14 body — best measured) ----------------
#define QSCALE 0.18033688011112042f   // 0.125 * log2(e)
#define ONES2  0x3C003C00u            // two fp16 1.0
#define SM_FULL0  (NSTG * TILE_B)         // full[4]: tx barriers
#define SM_EMPTY0 (NSTG * TILE_B + 32)    // empty[4]: 8 warp-arrival barriers
#define SM_TOTAL  (NSTG * TILE_B + 128)   // 65664 -> 2 CTAs/SM

extern __shared__ __align__(1024) char dynsm[];

template <bool MASKED>
__device__ __forceinline__ void tile_body(
    int t, int st, int rpar, int tmax_glob, uint32_t sm, const unsigned char* kvbase,
    const uint32_t Qh[4][4], const uint32_t koff[4], const uint32_t voff[4],
    const float zc[4],
    float Oa[8][4], float Dden[4],
    int tid, int lane, int rowglob)
{
    MBAR_WAIT(sm + SM_FULL0 + st * 8, rpar);

    const uint32_t stg = sm + (uint32_t)st * TILE_B;
    const uint32_t k_b = stg, v_b = stg + 8192;

    // ---- S = Q Kt (single fp16); kc=0 uses explicit zero-C ----
    float S[8][4];
    #pragma unroll
    for (int kc = 0; kc < 4; ++kc) {
        #pragma unroll
        for (int nbp = 0; nbp < 4; ++nbp) {
            uint32_t kb[4];
            ldsm4(k_b + koff[kc] + (uint32_t)nbp * 2048, kb);
            if (kc == 0) {
                mma16816hc(S[2*nbp],   Qh[0], kb[0], kb[1], zc);
                mma16816hc(S[2*nbp+1], Qh[0], kb[2], kb[3], zc);
            } else {
                mma16816h(S[2*nbp],   Qh[kc], kb[0], kb[1]);
                mma16816h(S[2*nbp+1], Qh[kc], kb[2], kb[3]);
            }
        }
    }

    // ---- prefetch V for kcs=0 (overlaps the exp MUFU stretch) ----
    uint32_t vbuf[2][4][4];
    #pragma unroll
    for (int nbp = 0; nbp < 4; ++nbp)
        ldsm4t(v_b + voff[nbp], vbuf[0][nbp]);

    // ---- exp; masked (future) slots contribute exp(0)=1 (reference semantics) ----
    const int quad = lane & 3;
    const int lim0 = MASKED ? (rowglob - (t << 6)) : 0;
    const int lim1 = lim0 + 8;
    uint32_t Ph[4][4];
    #pragma unroll
    for (int nb = 0; nb < 8; ++nb) {
        float p0, p1, p2, p3;
        if (MASKED) {
            int s0 = nb * 8 + quad * 2;
            p0 = (s0     <= lim0) ? ex2f(S[nb][0]) : 1.f;
            p1 = (s0 + 1 <= lim0) ? ex2f(S[nb][1]) : 1.f;
            p2 = (s0     <= lim1) ? ex2f(S[nb][2]) : 1.f;
            p3 = (s0 + 1 <= lim1) ? ex2f(S[nb][3]) : 1.f;
        } else {
            p0 = ex2f(S[nb][0]);
            p1 = ex2f(S[nb][1]);
            p2 = ex2f(S[nb][2]);
            p3 = ex2f(S[nb][3]);
        }
        Ph[nb >> 1][(nb & 1) * 2]     = packf16(p0, p1);
        Ph[nb >> 1][(nb & 1) * 2 + 1] = packf16(p2, p3);
    }

    // ---- den += P * ones (row sums on tensor pipe) ----
    #pragma unroll
    for (int kcs = 0; kcs < 4; ++kcs)
        mma16816h(Dden, Ph[kcs], ONES2, ONES2);

    // ---- O += P V (rotated V buffers) ----
    #pragma unroll
    for (int kcs = 0; kcs < 4; ++kcs) {
        if (kcs < 3) {
            #pragma unroll
            for (int nbp = 0; nbp < 4; ++nbp)
                ldsm4t(v_b + voff[nbp] + (uint32_t)(kcs + 1) * 2048, vbuf[(kcs + 1) & 1][nbp]);
        }
        #pragma unroll
        for (int nbp = 0; nbp < 4; ++nbp) {
            const uint32_t* vb = vbuf[kcs & 1][nbp];
            mma16816h(Oa[2*nbp],   Ph[kcs], vb[0], vb[1]);
            mma16816h(Oa[2*nbp+1], Ph[kcs], vb[2], vb[3]);
        }
    }

    if (lane == 0) MBAR_ARRIVE(sm + SM_EMPTY0 + st * 8);

    if (tid == 0 && t + NSTG <= tmax_glob) {
        MBAR_WAIT(sm + SM_EMPTY0 + st * 8, rpar);
        MBAR_EXPECT_TX(sm + SM_FULL0 + st * 8, TILE_B);
        bulk_ld(stg, kvbase + (size_t)(t + NSTG) * TILE_B, TILE_B, sm + SM_FULL0 + st * 8);
    }
}

__global__ void __launch_bounds__(256, 2) attn_mma(const float* __restrict__ Q,
                                                   float* __restrict__ O) {
    const uint32_t sm = smem_u32(dynsm);
    const int tid = threadIdx.x;
    const int w = tid >> 5, lane = tid & 31;
    const int g = lane >> 2, quad = lane & 3;
    const int bh = blockIdx.y, b = bh >> 4, h = bh & 15;
    const int mtile = (NQT - 1) - (int)blockIdx.x;   // heavy q-tiles first
    const int tmax_glob = 2 * mtile + 1;
    const int nproc = 2 * mtile + 2 - (w < 4 ? 1 : 0);   // tiles processed; last one MASKED

    if (tid == 0) {
        #pragma unroll
        for (int s = 0; s < NSTG; ++s) {
            MBAR_INIT(sm + SM_FULL0 + s * 8, 1);
            MBAR_INIT(sm + SM_EMPTY0 + s * 8, 8);
        }
    }
    __syncthreads();

    // prologue FIRST: TMA fills overlap the Q global loads below
    const unsigned char* kvbase = g_KV + (size_t)bh * NST * TILE_B;
    if (tid == 0) {
        #pragma unroll
        for (int s = 0; s < NSTG; ++s) {
            if (s <= tmax_glob) {
                MBAR_EXPECT_TX(sm + SM_FULL0 + s * 8, TILE_B);
                bulk_ld(sm + s * TILE_B, kvbase + (size_t)s * TILE_B, TILE_B,
                        sm + SM_FULL0 + s * 8);
            }
        }
    }

    // per-lane ldmatrix geometry, hoisted to offset tables
    const int ks_row = (lane & 7) + ((lane >> 4) << 3);
    const uint32_t k_col = ((uint32_t)((lane >> 3) & 1)) * 16;
    const int vs_row = (lane & 7) + (((lane >> 3) & 1) << 3);
    const uint32_t v_col = ((uint32_t)(lane >> 4)) << 4;
    const uint32_t xo = ((uint32_t)(lane & 7)) << 4;
    uint32_t koff[4], voff[4];
    #pragma unroll
    for (int kc = 0; kc < 4; ++kc)
        koff[kc] = (uint32_t)ks_row * 128 + (((uint32_t)kc * 32 + k_col) ^ xo);
    #pragma unroll
    for (int nbp = 0; nbp < 4; ++nbp)
        voff[nbp] = (uint32_t)vs_row * 128 + (((uint32_t)nbp * 32 + v_col) ^ xo);

    // ---- Q fragments (single fp16, scale folded in) ----
    uint32_t Qh[4][4];
    {
        const float* qb = Q + (((size_t)b * Lc + (size_t)mtile * BM + w * 16) * Hc + h) * 64;
        #pragma unroll
        for (int kc = 0; kc < 4; ++kc) {
            int e0 = kc * 16 + quad * 2;
            float2 v00 = *(const float2*)(qb + (size_t)g * 1024 + e0);
            float2 v10 = *(const float2*)(qb + (size_t)(g + 8) * 1024 + e0);
            float2 v01 = *(const float2*)(qb + (size_t)g * 1024 + e0 + 8);
            float2 v11 = *(const float2*)(qb + (size_t)(g + 8) * 1024 + e0 + 8);
            Qh[kc][0] = packf16(v00.x * QSCALE, v00.y * QSCALE);
            Qh[kc][1] = packf16(v10.x * QSCALE, v10.y * QSCALE);
            Qh[kc][2] = packf16(v01.x * QSCALE, v01.y * QSCALE);
            Qh[kc][3] = packf16(v11.x * QSCALE, v11.y * QSCALE);
        }
    }

    float Oa[8][4];
    #pragma unroll
    for (int i = 0; i < 8; ++i)
        #pragma unroll
        for (int j = 0; j < 4; ++j) Oa[i][j] = 0.f;
    float Dden[4] = {0.f, 0.f, 0.f, 0.f};
    const float zc[4] = {0.f, 0.f, 0.f, 0.f};

    const int rowA = w * 16 + g;
    const int rowglob = mtile * BM + rowA;

    int t = 0, st = 0, rp = 0;
    #pragma unroll 2
    for (; t < nproc - 1; ++t) {
        tile_body<false>(t, st, rp, tmax_glob, sm, kvbase, Qh, koff, voff, zc,
                         Oa, Dden, tid, lane, rowglob);
        if (++st == NSTG) { st = 0; rp ^= 1; }
    }
    tile_body<true>(t, st, rp, tmax_glob, sm, kvbase, Qh, koff, voff, zc,
                    Oa, Dden, tid, lane, rowglob);

    // ---- epilogue: direct suffix-sum of per-half-chunk V sums (no precomputed scan) ----
    // half-chunk hc covers s-rows [hc*32, hc*32+32); processed s < nproc*64 -> skip hc < 2*nproc
    float sfx2[8][2];
    #pragma unroll
    for (int nb = 0; nb < 8; ++nb) { sfx2[nb][0] = 0.f; sfx2[nb][1] = 0.f; }
    {
        const int d0base = quad * 2;
        #pragma unroll 1
        for (int hc = 2 * nproc; hc < 64; ++hc) {
            const float* pp = &g_part[(uint32_t)((bh << 6) + hc) << 6];
            #pragma unroll
            for (int nb = 0; nb < 8; ++nb) {
                float2 s2 = *(const float2*)(pp + nb * 8 + d0base);
                sfx2[nb][0] += s2.x;
                sfx2[nb][1] += s2.y;
            }
        }
    }

    const float corr = (float)(Lc - BN * nproc);   // masked slots beyond processed tiles
    const float inv0 = 1.f / (Dden[0] + corr);
    const float inv1 = 1.f / (Dden[2] + corr);

    const int r0g = rowglob;
    const int r1g = r0g + 8;
    const size_t ob0 = (((size_t)b * Lc + r0g) * Hc + h) * 64;
    const size_t ob1 = (((size_t)b * Lc + r1g) * Hc + h) * 64;

    #pragma unroll
    for (int nb = 0; nb < 8; ++nb) {
        int d0 = nb * 8 + quad * 2;
        float2 o0 = make_float2((Oa[nb][0] + sfx2[nb][0]) * inv0, (Oa[nb][1] + sfx2[nb][1]) * inv0);
        float2 o1 = make_float2((Oa[nb][2] + sfx2[nb][0]) * inv1, (Oa[nb][3] + sfx2[nb][1]) * inv1);
        *(float2*)&O[ob0 + d0] = o0;
        *(float2*)&O[ob1 + d0] = o1;
    }
}

// ---------------- launch ----------------
extern "C" void kernel_launch(void* const* d_in, const int* in_sizes, int n_in,
                              void* d_out, int out_size) {
    const float* Q = (const float*)d_in[0];
    const float* K = (const float*)d_in[1];
    const float* V = (const float*)d_in[2];
    float* O = (float*)d_out;

    convert_kv<<<2048, 256>>>(K, V);

    cudaFuncSetAttribute(attn_mma, cudaFuncAttributeMaxDynamicSharedMemorySize, SM_TOTAL);
    attn_mma<<<dim3(NQT, BHc), 256, SM_TOTAL>>>(Q, O);
}

// round 16
// speedup vs baseline: 1.0756x; 1.0166x over previous
#include <cuda_runtime.h>
#include <cuda_bf16.h>
#include <cstdint>

#define Bc 2
#define Lc 2048
#define Hc 16
#define BHc 32
#define BM 128                 // q-rows per CTA
#define BN 64                  // s-rows per tile
#define NQT 16                 // q tiles
#define NST 32                 // s tiles
#define TILE_B 16384           // packed tile: Kf16(8K)|Vf16(8K)
#define NSTG 4                 // pipeline stages

// ---------------- device scratch ----------------
__device__ float g_part[2048 * 64];                             // per-half-chunk (32 s-rows) V column sums
__device__ unsigned char g_KV[(size_t)BHc * NST * TILE_B];      // pre-swizzled packed KV (16MB)

// ---------------- helpers ----------------
__device__ __forceinline__ uint32_t smem_u32(const void* p) {
    uint32_t a;
    asm("{ .reg .u64 t; cvta.to.shared.u64 t, %1; cvt.u32.u64 %0, t; }" : "=r"(a) : "l"(p));
    return a;
}
__device__ __forceinline__ float ex2f(float x) {
    float y; asm("ex2.approx.f32 %0, %1;" : "=f"(y) : "f"(x)); return y;
}
__device__ __forceinline__ uint32_t packf16(float lo, float hi) {
    uint32_t r;
    asm("cvt.rn.f16x2.f32 %0, %1, %2;" : "=r"(r) : "f"(hi), "f"(lo));
    return r;
}
// accumulate form: d += a*b
__device__ __forceinline__ void mma16816h(float* c, const uint32_t* a, uint32_t b0, uint32_t b1) {
    asm volatile("mma.sync.aligned.m16n8k16.row.col.f32.f16.f16.f32 "
        "{%0,%1,%2,%3}, {%4,%5,%6,%7}, {%8,%9}, {%0,%1,%2,%3};"
        : "+f"(c[0]), "+f"(c[1]), "+f"(c[2]), "+f"(c[3])
        : "r"(a[0]), "r"(a[1]), "r"(a[2]), "r"(a[3]), "r"(b0), "r"(b1));
}
// explicit-C form: d = a*b + c  (pinned zero C skips S pre-zeroing)
__device__ __forceinline__ void mma16816hc(float* d, const uint32_t* a, uint32_t b0, uint32_t b1,
                                           const float* c) {
    asm volatile("mma.sync.aligned.m16n8k16.row.col.f32.f16.f16.f32 "
        "{%0,%1,%2,%3}, {%4,%5,%6,%7}, {%8,%9}, {%10,%11,%12,%13};"
        : "=f"(d[0]), "=f"(d[1]), "=f"(d[2]), "=f"(d[3])
        : "r"(a[0]), "r"(a[1]), "r"(a[2]), "r"(a[3]), "r"(b0), "r"(b1),
          "f"(c[0]), "f"(c[1]), "f"(c[2]), "f"(c[3]));
}
__device__ __forceinline__ void ldsm4(uint32_t addr, uint32_t* r) {
    asm volatile("ldmatrix.sync.aligned.m8n8.x4.shared.b16 {%0,%1,%2,%3}, [%4];"
        : "=r"(r[0]), "=r"(r[1]), "=r"(r[2]), "=r"(r[3]) : "r"(addr));
}
__device__ __forceinline__ void ldsm4t(uint32_t addr, uint32_t* r) {
    asm volatile("ldmatrix.sync.aligned.m8n8.x4.trans.shared.b16 {%0,%1,%2,%3}, [%4];"
        : "=r"(r[0]), "=r"(r[1]), "=r"(r[2]), "=r"(r[3]) : "r"(addr));
}
__device__ __forceinline__ void bulk_ld(uint32_t dst, const void* src, uint32_t bytes, uint32_t mbar) {
    asm volatile("cp.async.bulk.shared::cluster.global.mbarrier::complete_tx::bytes [%0], [%1], %2, [%3];"
        :: "r"(dst), "l"(src), "r"(bytes), "r"(mbar) : "memory");
}
#define MBAR_INIT(addr, cnt) \
    asm volatile("mbarrier.init.shared.b64 [%0], %1;" :: "r"((uint32_t)(addr)), "r"((uint32_t)(cnt)) : "memory")
#define MBAR_EXPECT_TX(addr, tx) \
    asm volatile("mbarrier.arrive.expect_tx.shared.b64 _, [%0], %1;" :: "r"((uint32_t)(addr)), "r"((uint32_t)(tx)) : "memory")
#define MBAR_ARRIVE(addr) \
    asm volatile("mbarrier.arrive.shared.b64 _, [%0];" :: "r"((uint32_t)(addr)) : "memory")
#define MBAR_WAIT(addr, par) do { \
    uint32_t _m = (uint32_t)(addr); uint32_t _p = (uint32_t)(par); uint32_t _d; \
    asm volatile("{ .reg .pred p; mbarrier.try_wait.parity.acquire.cta.shared::cta.b64 p, [%1], %2; selp.b32 %0,1,0,p; }" \
        : "=r"(_d) : "r"(_m), "r"(_p) : "memory"); \
    if (!_d) { \
        asm volatile("{ .reg .pred P1; WL_%=: mbarrier.try_wait.parity.acquire.cta.shared::cta.b64 P1, [%0], %1, 0x989680; @P1 bra.uni WD_%=; bra.uni WL_%=; WD_%=: }" \
            :: "r"(_m), "r"(_p) : "memory"); \
    } } while (0)

// ---------------- preprocessing: convert + per-block V sums (validated R15) ----------------
__global__ void convert_kv(const float* __restrict__ K, const float* __restrict__ V) {
    __shared__ float vsum[32 * 64];                  // [s_local 32][d 64]
    uint32_t n = blockIdx.x * 256 + threadIdx.x;     // 524288 threads
    int ch = n & 7;
    int s  = (n >> 3) & 2047;
    int bh = n >> 14;                                // == blockIdx.x >> 6
    int b = bh >> 4, h = bh & 15;
    int t = s >> 6, sr = s & 63;

    size_t src = (((size_t)b * Lc + s) * Hc + h) * 64 + ch * 8;
    size_t tb = ((size_t)(bh * NST + t)) * TILE_B;
    uint32_t roff = (uint32_t)sr * 128 + (((uint32_t)ch * 16) ^ (((uint32_t)sr & 7) << 4));

    float4 k0 = *(const float4*)(K + src), k1 = *(const float4*)(K + src + 4);
    float4 v0 = *(const float4*)(V + src), v1 = *(const float4*)(V + src + 4);

    uint4 kh, vh;
    kh.x = packf16(k0.x, k0.y); kh.y = packf16(k0.z, k0.w);
    kh.z = packf16(k1.x, k1.y); kh.w = packf16(k1.z, k1.w);
    vh.x = packf16(v0.x, v0.y); vh.y = packf16(v0.z, v0.w);
    vh.z = packf16(v1.x, v1.y); vh.w = packf16(v1.z, v1.w);

    *(uint4*)(g_KV + tb +    0 + roff) = kh;
    *(uint4*)(g_KV + tb + 8192 + roff) = vh;

    // block-level V column sums (32 s-rows per block) -> g_part[blockIdx.x][d]
    int sl = threadIdx.x >> 3;
    float* vs = &vsum[sl * 64 + ch * 8];
    *(float4*)&vs[0] = v0;
    *(float4*)&vs[4] = v1;
    __syncthreads();
    if (threadIdx.x < 64) {
        float acc = 0.f;
        #pragma unroll 8
        for (int r = 0; r < 32; ++r) acc += vsum[r * 64 + threadIdx.x];
        g_part[(uint32_t)blockIdx.x * 64 + threadIdx.x] = acc;
    }
}

// ---------------- main attention kernel ----------------
#define QSCALE 0.18033688011112042f   // 0.125 * log2(e)
#define ONES2  0x3C003C00u            // two fp16 1.0
#define SM_FULL0  (NSTG * TILE_B)         // full[4]: tx barriers
#define SM_EMPTY0 (NSTG * TILE_B + 32)    // empty[4]: 8 warp-arrival barriers
#define SM_TOTAL  (NSTG * TILE_B + 128)   // 65664 -> 2 CTAs/SM

extern __shared__ __align__(1024) char dynsm[];

template <bool MASKED>
__device__ __forceinline__ void tile_body(
    int t, int st, int rpar, int tmax_glob, uint32_t sm, const unsigned char* kvbase,
    const uint32_t Qh[4][4], const uint32_t koff[4], const uint32_t voff[4],
    const float zc[4],
    float Oa[8][4], float Dden[4],
    int tid, int lane, int rowglob)
{
    MBAR_WAIT(sm + SM_FULL0 + st * 8, rpar);

    const uint32_t stg = sm + (uint32_t)st * TILE_B;
    const uint32_t k_b = stg, v_b = stg + 8192;

    // ---- S = Q Kt (single fp16); kc=0 uses explicit zero-C ----
    float S[8][4];
    #pragma unroll
    for (int kc = 0; kc < 4; ++kc) {
        #pragma unroll
        for (int nbp = 0; nbp < 4; ++nbp) {
            uint32_t kb[4];
            ldsm4(k_b + koff[kc] + (uint32_t)nbp * 2048, kb);
            if (kc == 0) {
                mma16816hc(S[2*nbp],   Qh[0], kb[0], kb[1], zc);
                mma16816hc(S[2*nbp+1], Qh[0], kb[2], kb[3], zc);
            } else {
                mma16816h(S[2*nbp],   Qh[kc], kb[0], kb[1]);
                mma16816h(S[2*nbp+1], Qh[kc], kb[2], kb[3]);
            }
        }
    }

    // ---- prefetch V for kcs=0 (overlaps the exp MUFU stretch) ----
    uint32_t vbuf[2][4][4];
    #pragma unroll
    for (int nbp = 0; nbp < 4; ++nbp)
        ldsm4t(v_b + voff[nbp], vbuf[0][nbp]);

    // ---- exp; masked (future) slots contribute exp(0)=1 (reference semantics) ----
    const int quad = lane & 3;
    const int lim0 = MASKED ? (rowglob - (t << 6)) : 0;
    const int lim1 = lim0 + 8;
    uint32_t Ph[4][4];
    #pragma unroll
    for (int nb = 0; nb < 8; ++nb) {
        float p0, p1, p2, p3;
        if (MASKED) {
            int s0 = nb * 8 + quad * 2;
            p0 = (s0     <= lim0) ? ex2f(S[nb][0]) : 1.f;
            p1 = (s0 + 1 <= lim0) ? ex2f(S[nb][1]) : 1.f;
            p2 = (s0     <= lim1) ? ex2f(S[nb][2]) : 1.f;
            p3 = (s0 + 1 <= lim1) ? ex2f(S[nb][3]) : 1.f;
        } else {
            p0 = ex2f(S[nb][0]);
            p1 = ex2f(S[nb][1]);
            p2 = ex2f(S[nb][2]);
            p3 = ex2f(S[nb][3]);
        }
        Ph[nb >> 1][(nb & 1) * 2]     = packf16(p0, p1);
        Ph[nb >> 1][(nb & 1) * 2 + 1] = packf16(p2, p3);
    }

    // ---- O += P V, den += P*ones; den MMA fills the tensor pipe during each
    //      slice's V-ldsm window (its operands are ready immediately) ----
    #pragma unroll
    for (int kcs = 0; kcs < 4; ++kcs) {
        if (kcs < 3) {
            #pragma unroll
            for (int nbp = 0; nbp < 4; ++nbp)
                ldsm4t(v_b + voff[nbp] + (uint32_t)(kcs + 1) * 2048, vbuf[(kcs + 1) & 1][nbp]);
        }
        mma16816h(Dden, Ph[kcs], ONES2, ONES2);
        #pragma unroll
        for (int nbp = 0; nbp < 4; ++nbp) {
            const uint32_t* vb = vbuf[kcs & 1][nbp];
            mma16816h(Oa[2*nbp],   Ph[kcs], vb[0], vb[1]);
            mma16816h(Oa[2*nbp+1], Ph[kcs], vb[2], vb[3]);
        }
    }

    if (lane == 0) MBAR_ARRIVE(sm + SM_EMPTY0 + st * 8);

    if (tid == 0 && t + NSTG <= tmax_glob) {
        MBAR_WAIT(sm + SM_EMPTY0 + st * 8, rpar);
        MBAR_EXPECT_TX(sm + SM_FULL0 + st * 8, TILE_B);
        bulk_ld(stg, kvbase + (size_t)(t + NSTG) * TILE_B, TILE_B, sm + SM_FULL0 + st * 8);
    }
}

__global__ void __launch_bounds__(256, 2) attn_mma(const float* __restrict__ Q,
                                                   float* __restrict__ O) {
    const uint32_t sm = smem_u32(dynsm);
    const int tid = threadIdx.x;
    const int w = tid >> 5, lane = tid & 31;
    const int g = lane >> 2, quad = lane & 3;
    const int bh = blockIdx.y, b = bh >> 4, h = bh & 15;
    const int mtile = (NQT - 1) - (int)blockIdx.x;   // heavy q-tiles first
    const int tmax_glob = 2 * mtile + 1;
    const int nproc = 2 * mtile + 2 - (w < 4 ? 1 : 0);   // tiles processed; last one MASKED

    if (tid == 0) {
        #pragma unroll
        for (int s = 0; s < NSTG; ++s) {
            MBAR_INIT(sm + SM_FULL0 + s * 8, 1);
            MBAR_INIT(sm + SM_EMPTY0 + s * 8, 8);
        }
    }
    __syncthreads();

    // prologue FIRST: TMA fills overlap the Q global loads below
    const unsigned char* kvbase = g_KV + (size_t)bh * NST * TILE_B;
    if (tid == 0) {
        #pragma unroll
        for (int s = 0; s < NSTG; ++s) {
            if (s <= tmax_glob) {
                MBAR_EXPECT_TX(sm + SM_FULL0 + s * 8, TILE_B);
                bulk_ld(sm + s * TILE_B, kvbase + (size_t)s * TILE_B, TILE_B,
                        sm + SM_FULL0 + s * 8);
            }
        }
    }

    // per-lane ldmatrix geometry, hoisted to offset tables
    const int ks_row = (lane & 7) + ((lane >> 4) << 3);
    const uint32_t k_col = ((uint32_t)((lane >> 3) & 1)) * 16;
    const int vs_row = (lane & 7) + (((lane >> 3) & 1) << 3);
    const uint32_t v_col = ((uint32_t)(lane >> 4)) << 4;
    const uint32_t xo = ((uint32_t)(lane & 7)) << 4;
    uint32_t koff[4], voff[4];
    #pragma unroll
    for (int kc = 0; kc < 4; ++kc)
        koff[kc] = (uint32_t)ks_row * 128 + (((uint32_t)kc * 32 + k_col) ^ xo);
    #pragma unroll
    for (int nbp = 0; nbp < 4; ++nbp)
        voff[nbp] = (uint32_t)vs_row * 128 + (((uint32_t)nbp * 32 + v_col) ^ xo);

    // ---- Q fragments (single fp16, scale folded in) ----
    uint32_t Qh[4][4];
    {
        const float* qb = Q + (((size_t)b * Lc + (size_t)mtile * BM + w * 16) * Hc + h) * 64;
        #pragma unroll
        for (int kc = 0; kc < 4; ++kc) {
            int e0 = kc * 16 + quad * 2;
            float2 v00 = *(const float2*)(qb + (size_t)g * 1024 + e0);
            float2 v10 = *(const float2*)(qb + (size_t)(g + 8) * 1024 + e0);
            float2 v01 = *(const float2*)(qb + (size_t)g * 1024 + e0 + 8);
            float2 v11 = *(const float2*)(qb + (size_t)(g + 8) * 1024 + e0 + 8);
            Qh[kc][0] = packf16(v00.x * QSCALE, v00.y * QSCALE);
            Qh[kc][1] = packf16(v10.x * QSCALE, v10.y * QSCALE);
            Qh[kc][2] = packf16(v01.x * QSCALE, v01.y * QSCALE);
            Qh[kc][3] = packf16(v11.x * QSCALE, v11.y * QSCALE);
        }
    }

    float Oa[8][4];
    #pragma unroll
    for (int i = 0; i < 8; ++i)
        #pragma unroll
        for (int j = 0; j < 4; ++j) Oa[i][j] = 0.f;
    float Dden[4] = {0.f, 0.f, 0.f, 0.f};
    const float zc[4] = {0.f, 0.f, 0.f, 0.f};

    const int rowA = w * 16 + g;
    const int rowglob = mtile * BM + rowA;

    int t = 0, st = 0, rp = 0;
    #pragma unroll 4
    for (; t < nproc - 1; ++t) {
        tile_body<false>(t, st, rp, tmax_glob, sm, kvbase, Qh, koff, voff, zc,
                         Oa, Dden, tid, lane, rowglob);
        if (++st == NSTG) { st = 0; rp ^= 1; }
    }
    tile_body<true>(t, st, rp, tmax_glob, sm, kvbase, Qh, koff, voff, zc,
                    Oa, Dden, tid, lane, rowglob);

    // ---- epilogue: direct suffix-sum of per-half-chunk V sums (validated R15) ----
    float sfx2[8][2];
    #pragma unroll
    for (int nb = 0; nb < 8; ++nb) { sfx2[nb][0] = 0.f; sfx2[nb][1] = 0.f; }
    {
        const int d0base = quad * 2;
        #pragma unroll 1
        for (int hc = 2 * nproc; hc < 64; ++hc) {
            const float* pp = &g_part[(uint32_t)((bh << 6) + hc) << 6];
            #pragma unroll
            for (int nb = 0; nb < 8; ++nb) {
                float2 s2 = *(const float2*)(pp + nb * 8 + d0base);
                sfx2[nb][0] += s2.x;
                sfx2[nb][1] += s2.y;
            }
        }
    }

    const float corr = (float)(Lc - BN * nproc);   // masked slots beyond processed tiles
    const float inv0 = 1.f / (Dden[0] + corr);
    const float inv1 = 1.f / (Dden[2] + corr);

    const int r0g = rowglob;
    const int r1g = r0g + 8;
    const size_t ob0 = (((size_t)b * Lc + r0g) * Hc + h) * 64;
    const size_t ob1 = (((size_t)b * Lc + r1g) * Hc + h) * 64;

    #pragma unroll
    for (int nb = 0; nb < 8; ++nb) {
        int d0 = nb * 8 + quad * 2;
        float2 o0 = make_float2((Oa[nb][0] + sfx2[nb][0]) * inv0, (Oa[nb][1] + sfx2[nb][1]) * inv0);
        float2 o1 = make_float2((Oa[nb][2] + sfx2[nb][0]) * inv1, (Oa[nb][3] + sfx2[nb][1]) * inv1);
        *(float2*)&O[ob0 + d0] = o0;
        *(float2*)&O[ob1 + d0] = o1;
    }
}

// ---------------- launch ----------------
extern "C" void kernel_launch(void* const* d_in, const int* in_sizes, int n_in,
                              void* d_out, int out_size) {
    const float* Q = (const float*)d_in[0];
    const float* K = (const float*)d_in[1];
    const float* V = (const float*)d_in[2];
    float* O = (float*)d_out;

    convert_kv<<<2048, 256>>>(K, V);

    cudaFuncSetAttribute(attn_mma, cudaFuncAttributeMaxDynamicSharedMemorySize, SM_TOTAL);
    attn_mma<<<dim3(NQT, BHc), 256, SM_TOTAL>>>(Q, O);
}